// round 13
// baseline (speedup 1.0000x reference)
#include <cuda_runtime.h>
#include <math.h>
#include <stdint.h>

// Problem constants (fixed by setup_inputs)
#define HID     256
#define NVOCAB  35
#define PADIDX  34
#define NSEQ    128      // B*P = 16*8
#define TLEN    256
#define TOUT    255
#define ROWS7   1792     // 7*HID
#define NCTA    128      // 16 unit-groups x 8 seq-groups
#define NTHR    256
#define UPC     16       // hidden units per CTA
#define SPC     16       // sequences per CTA
#define RPC     112      // 7*UPC real rows per CTA
#define RPAD    128      // padded rows (16 garbage rows, never read)
#define PSTR    132      // padded part stride
#define NGRP    8
#define CPG     16       // CTAs per seq-group (barrier width)
#define BPAD    128      // barrier line padding (ints) = 512 B per group

// ---- device globals (no allocations allowed) ----
__device__ float    g_ZE[NVOCAB * ROWS7];   // b[r] + Emb[v,:] . W[r, 0:256]
__device__ float    g_hT[HID * NSEQ];       // h exchange, TRANSPOSED: [unit][seqG]
__device__ unsigned g_cnt[NGRP * BPAD];     // per-group arrival counters (padded lines)
__device__ unsigned g_ep[NGRP * BPAD];      // per-group epochs (padded lines)

// ---- packed f32x2 helpers (Blackwell FFMA2 path) ----
__device__ __forceinline__ unsigned long long pkdup(float a) {
    unsigned long long r;
    asm("mov.b64 %0, {%1, %1};" : "=l"(r) : "f"(a));
    return r;
}
__device__ __forceinline__ void fma2(unsigned long long& d,
                                     unsigned long long a, unsigned long long b) {
    asm("fma.rn.f32x2 %0, %1, %2, %0;" : "+l"(d) : "l"(a), "l"(b));
}
__device__ __forceinline__ float2 up2(unsigned long long v) {
    float2 f;
    asm("mov.b64 {%0, %1}, %2;" : "=f"(f.x), "=f"(f.y) : "l"(v));
    return f;
}
__device__ __forceinline__ float sigm(float x) { return 1.0f / (1.0f + __expf(-x)); }
__device__ __forceinline__ unsigned ld_acq(const unsigned* p) {
    unsigned v;
    asm volatile("ld.acquire.gpu.u32 %0, [%1];" : "=r"(v) : "l"(p) : "memory");
    return v;
}

// =====================================================================
// Kernel 1: ZE[v][r] = b[r] + sum_c Emb[v,c] * W[r,c]   (c in [0,256))
// =====================================================================
#define ZE_SWP 260
__global__ void __launch_bounds__(256) ze_kernel(const float* __restrict__ Emb,
                                                 const float* __restrict__ W,
                                                 const float* __restrict__ bias) {
    extern __shared__ float zsm[];
    float* sE = zsm;                    // 35*256 floats
    float* sW = zsm + NVOCAB * HID;     // 128*ZE_SWP floats
    const int tid = threadIdx.x, blk = blockIdx.x;

    for (int i = tid; i < (NVOCAB * HID) / 4; i += 256)
        *(float4*)&sE[i * 4] = *(const float4*)(Emb + i * 4);
    for (int i = tid; i < 128 * 64; i += 256) {
        int rl = i >> 6, c4 = i & 63;
        *(float4*)&sW[rl * ZE_SWP + c4 * 4] =
            *(const float4*)(W + (size_t)(blk * 128 + rl) * 512 + c4 * 4);
    }
    __syncthreads();

    for (int i = tid; i < 128 * NVOCAB; i += 256) {
        int rl = i % 128, v = i / 128;
        const float* we = sW + rl * ZE_SWP;
        const float* ee = sE + v * HID;
        float acc = 0.f;
        #pragma unroll 8
        for (int c = 0; c < HID; c++) acc = fmaf(we[c], ee[c], acc);
        g_ZE[v * ROWS7 + blk * 128 + rl] = acc + bias[blk * 128 + rl];
    }
}

// =====================================================================
// Kernel 2: persistent CT-LSTM reverse scan (R7 matvec core).
// 128 CTAs: cta = sg*16 + ug.  ug owns 16 hidden units (112 W rows in smem),
// sg owns 16 sequences.  Per-sg barriers on PRIVATE 512B lines.
// =====================================================================
#define SM_WS    (RPAD * HID)        // 32768 f : Ws[c*128 + rloc]
#define SM_HT    (HID * SPC)         //  4096 f : hT[c*16 + s]
#define SM_PART  (4 * SPC * PSTR)    //  8448 f : part[(kq*16+s)*132 + rloc]
#define SM_ZES   (NVOCAB * RPC)      //  3920 f
#define SM_EVS   (SPC * TLEN)        //  4096 (ints)
#define SM_DTS   (SPC * TLEN)        //  4096 f
#define SMEM_MAIN ((SM_WS + SM_HT + SM_PART + SM_ZES + SM_EVS + SM_DTS) * 4)

__global__ void __launch_bounds__(NTHR, 1)
ctlstm_kernel(const int* __restrict__ ev, const float* __restrict__ dtime,
              const float* __restrict__ W, float* __restrict__ out) {
    extern __shared__ float sm[];
    float* Ws   = sm;
    float* hT   = Ws + SM_WS;
    float* part = hT + SM_HT;
    float* ZEs  = part + SM_PART;
    int*   evs  = (int*)(ZEs + SM_ZES);
    float* dts  = (float*)(evs + SM_EVS);

    const int tid = threadIdx.x;
    const int cta = blockIdx.x;
    const int ug  = cta & 15;
    const int sg  = cta >> 4;

    unsigned* cntp = &g_cnt[sg * BPAD];
    unsigned* epp  = &g_ep[sg * BPAD];

    // pre-arrival epoch snapshot (all threads; replay-safe)
    const unsigned epoch0 = *(volatile unsigned*)epp;

    // ---- init: W slice (rows g*256 + ug*16+u, cols 256..511), c-major
    for (int i = tid; i < RPC * 64; i += NTHR) {
        int rl = i >> 6, c4 = i & 63;
        int g = rl >> 4, u = rl & 15;
        size_t rg = (size_t)(g * HID + ug * UPC + u);
        float4 w4 = *(const float4*)(W + rg * 512 + 256 + c4 * 4);
        Ws[(c4 * 4 + 0) * RPAD + rl] = w4.x;
        Ws[(c4 * 4 + 1) * RPAD + rl] = w4.y;
        Ws[(c4 * 4 + 2) * RPAD + rl] = w4.z;
        Ws[(c4 * 4 + 3) * RPAD + rl] = w4.w;
    }
    for (int i = tid; i < 16 * HID; i += NTHR) {            // zero pad rows
        int rl = RPC + (i & 15), c = i >> 4;
        Ws[c * RPAD + rl] = 0.f;
    }
    for (int i = tid; i < NVOCAB * RPC; i += NTHR) {        // ZE slice
        int v = i / RPC, rl = i % RPC;
        int g = rl >> 4, u = rl & 15;
        ZEs[v * RPC + rl] = g_ZE[v * ROWS7 + g * HID + ug * UPC + u];
    }
    for (int i = tid; i < SPC * TLEN / 4; i += NTHR) {      // event/dtime cache
        int s = i >> 6, c4 = i & 63;
        int seq = sg * SPC + s;
        *(int4*)&evs[s * TLEN + c4 * 4]   = *(const int4*)(ev + (size_t)seq * TLEN + c4 * 4);
        *(float4*)&dts[s * TLEN + c4 * 4] = *(const float4*)(dtime + (size_t)seq * TLEN + c4 * 4);
    }
    for (int i = tid; i < HID * SPC; i += NTHR) hT[i] = 0.f;   // h_plus starts 0
    __syncthreads();

    // matvec decomposition: warp = (kk, sb); lane rb = 4-row block
    const int kk = tid >> 6;           // K quarter: c in [kk*64, kk*64+64)
    const int sb = (tid >> 5) & 1;     // seq half: seqs [sb*8, sb*8+8)
    const int rb = tid & 31;           // rows [rb*4, rb*4+4)
    const int c0 = kk * 64;

    // reduce/gates decomposition: tid = s*16 + u
    const int s_id = tid >> 4;
    const int u_id = tid & 15;
    const int seqG  = sg * SPC + s_id;
    const int unitG = ug * UPC + u_id;
    const long long TS    = (long long)NSEQ * TOUT * HID;
    const long long obase = (long long)seqG * (TOUT * HID) + unitG;

    float cprev = 0.f, cbprev = 0.f;
    unsigned phase = 0;

    for (int t = TOUT - 1; t >= 0; --t) {
        // ---------- matvec: part = Ws-slice @ hT ----------
        unsigned long long acc[4][4];
        #pragma unroll
        for (int r = 0; r < 4; r++)
            #pragma unroll
            for (int p = 0; p < 4; p++) acc[r][p] = 0ull;

        const float* wp = Ws + c0 * RPAD + rb * 4;
        const ulonglong2* hp = (const ulonglong2*)(hT + c0 * 16 + sb * 8);
        #pragma unroll 4
        for (int c = 0; c < 64; ++c) {
            float4 w = *(const float4*)wp;  wp += RPAD;
            ulonglong2 hA = hp[0];
            ulonglong2 hB = hp[1];
            hp += 4;
            unsigned long long wd0 = pkdup(w.x), wd1 = pkdup(w.y);
            unsigned long long wd2 = pkdup(w.z), wd3 = pkdup(w.w);
            fma2(acc[0][0], wd0, hA.x); fma2(acc[1][0], wd1, hA.x);
            fma2(acc[2][0], wd2, hA.x); fma2(acc[3][0], wd3, hA.x);
            fma2(acc[0][1], wd0, hA.y); fma2(acc[1][1], wd1, hA.y);
            fma2(acc[2][1], wd2, hA.y); fma2(acc[3][1], wd3, hA.y);
            fma2(acc[0][2], wd0, hB.x); fma2(acc[1][2], wd1, hB.x);
            fma2(acc[2][2], wd2, hB.x); fma2(acc[3][2], wd3, hB.x);
            fma2(acc[0][3], wd0, hB.y); fma2(acc[1][3], wd1, hB.y);
            fma2(acc[2][3], wd2, hB.y); fma2(acc[3][3], wd3, hB.y);
        }
        #pragma unroll
        for (int p = 0; p < 4; p++) {
            float2 p0 = up2(acc[0][p]), p1 = up2(acc[1][p]);
            float2 p2 = up2(acc[2][p]), p3 = up2(acc[3][p]);
            float4 e4 = make_float4(p0.x, p1.x, p2.x, p3.x);
            float4 o4 = make_float4(p0.y, p1.y, p2.y, p3.y);
            *(float4*)&part[(kk * 16 + sb * 8 + 2 * p)     * PSTR + rb * 4] = e4;
            *(float4*)&part[(kk * 16 + sb * 8 + 2 * p + 1) * PSTR + rb * 4] = o4;
        }
        __syncthreads();

        // ---------- reduce + minimal chain to h ----------
        const int   e  = evs[s_id * TLEN + t + 1];
        const float dt = dts[s_id * TLEN + t + 1];
        float z[7];
        #pragma unroll
        for (int g = 0; g < 7; ++g) {
            int rl = g * 16 + u_id;
            float a = ZEs[e * RPC + rl];
            a += part[(0 * 16 + s_id) * PSTR + rl];
            a += part[(1 * 16 + s_id) * PSTR + rl];
            a += part[(2 * 16 + s_id) * PSTR + rl];
            a += part[(3 * 16 + s_id) * PSTR + rl];
            z[g] = a;
        }
        float gi  = sigm(z[0]);
        float gf  = sigm(z[1]);
        float go  = sigm(z[2]);
        float gz  = tanhf(z[3]);
        float gib = sigm(z[4]);
        float gfb = sigm(z[5]);
        float gd  = fmaxf(z[6], 0.f) + log1pf(__expf(-fabsf(z[6])));   // softplus

        float cell = gf * cprev + gi * gz;
        float cbar = gfb * cbprev + gib * gz;
        float dec  = __expf(-gd * dt);
        float cnx  = cbar + (cell - cbar) * dec;
        float h    = go * tanhf(cnx);
        float m    = (e != PADIDX) ? 1.f : 0.f;
        cnx *= m; cbar *= m; h *= m;

        long long ob = obase + (long long)t * HID;

        if (t > 0) {
            // publish h TRANSPOSED immediately: g_hT[unit][seqG]
            __stcg(&g_hT[(size_t)unitG * NSEQ + seqG], h);
            __threadfence();
            __syncthreads();
            // arrive FIRST (tid0), then everyone drains outputs, then all spin
            if (tid == 0) {
                unsigned old = atomicAdd(cntp, 1u);
                if (old == CPG - 1) {
                    *(volatile unsigned*)cntp = 0u;
                    __threadfence();
                    atomicAdd(epp, 1u);
                }
            }
            ++phase;

            // deferred math + outputs overlap the barrier window
            float hmin = go * tanhf(cell);
            out[ob]          = cell;
            out[TS + ob]     = cbar;
            out[2 * TS + ob] = gd;
            out[3 * TS + ob] = go;
            out[4 * TS + ob] = h;
            out[5 * TS + ob] = hmin;
            cprev = cnx; cbprev = cbar;

            // all-thread acquire spin on the group's private epoch line
            while (ld_acq(epp) - epoch0 < phase) { }

            // reload hT[c*16+s] — conflict-free contiguous STS.128
            for (int i = tid; i < (HID * SPC) / 4; i += NTHR) {
                int c = i >> 2, s4 = (i & 3) * 4;
                float4 hv = __ldcg((const float4*)(g_hT + (size_t)c * NSEQ + sg * SPC + s4));
                *(float4*)&hT[c * 16 + s4] = hv;
            }
            __syncthreads();
        } else {
            float hmin = go * tanhf(cell);
            out[ob]          = cell;
            out[TS + ob]     = cbar;
            out[2 * TS + ob] = gd;
            out[3 * TS + ob] = go;
            out[4 * TS + ob] = h;
            out[5 * TS + ob] = hmin;
        }
    }
}

// =====================================================================
extern "C" void kernel_launch(void* const* d_in, const int* in_sizes, int n_in,
                              void* d_out, int out_size) {
    const int*   ev    = (const int*)d_in[0];     // event_obs [16,8,256] int32
    const float* dt    = (const float*)d_in[1];   // dtime_obs [16,8,256]
    const float* Emb   = (const float*)d_in[2];   // [35,256]
    const float* W     = (const float*)d_in[3];   // [1792,512]
    const float* bias  = (const float*)d_in[4];   // [1792]
    float*       out   = (float*)d_out;           // 6 x [16,8,255,256]

    (void)in_sizes; (void)n_in; (void)out_size;

    const int ze_smem = (NVOCAB * HID + 128 * ZE_SWP) * 4;   // 168,960 B
    cudaFuncSetAttribute(ze_kernel, cudaFuncAttributeMaxDynamicSharedMemorySize, ze_smem);
    cudaFuncSetAttribute(ctlstm_kernel, cudaFuncAttributeMaxDynamicSharedMemorySize, SMEM_MAIN);

    ze_kernel<<<ROWS7 / 128, 256, ze_smem>>>(Emb, W, bias);
    ctlstm_kernel<<<NCTA, NTHR, SMEM_MAIN>>>(ev, dt, W, out);
}

// round 14
// speedup vs baseline: 1.0077x; 1.0077x over previous
#include <cuda_runtime.h>
#include <math.h>
#include <stdint.h>

// Problem constants (fixed by setup_inputs)
#define HID     256
#define NVOCAB  35
#define PADIDX  34
#define NSEQ    128      // B*P = 16*8
#define TLEN    256
#define TOUT    255
#define ROWS7   1792     // 7*HID
#define NCTA    128      // 16 unit-groups x 8 seq-groups
#define NTHR    256
#define UPC     16       // hidden units per CTA
#define SPC     16       // sequences per CTA
#define RPC     112      // 7*UPC real rows per CTA
#define RPAD    128      // padded rows (16 garbage rows, never read)
#define PSTR    132      // padded part stride
#define NGRP    8
#define CPG     16       // CTAs per seq-group (barrier width)
#define BPAD    128      // barrier line padding (ints) = 512 B per group

// ---- device globals (no allocations allowed) ----
__device__ float    g_ZE[NVOCAB * ROWS7];   // b[r] + Emb[v,:] . W[r, 0:256]
__device__ float    g_hT[HID * NSEQ];       // h exchange, TRANSPOSED: [unit][seqG]
__device__ unsigned g_cnt[NGRP * BPAD];     // per-group arrival counters (padded lines)
__device__ unsigned g_ep[NGRP * BPAD];      // per-group epochs (padded lines)

// ---- packed f32x2 helpers (Blackwell FFMA2 path) ----
__device__ __forceinline__ unsigned long long pkdup(float a) {
    unsigned long long r;
    asm("mov.b64 %0, {%1, %1};" : "=l"(r) : "f"(a));
    return r;
}
__device__ __forceinline__ void fma2(unsigned long long& d,
                                     unsigned long long a, unsigned long long b) {
    asm("fma.rn.f32x2 %0, %1, %2, %0;" : "+l"(d) : "l"(a), "l"(b));
}
__device__ __forceinline__ float2 up2(unsigned long long v) {
    float2 f;
    asm("mov.b64 {%0, %1}, %2;" : "=f"(f.x), "=f"(f.y) : "l"(v));
    return f;
}
__device__ __forceinline__ float sigm(float x) { return 1.0f / (1.0f + __expf(-x)); }
__device__ __forceinline__ unsigned ld_acq(const unsigned* p) {
    unsigned v;
    asm volatile("ld.acquire.gpu.u32 %0, [%1];" : "=r"(v) : "l"(p) : "memory");
    return v;
}

// =====================================================================
// Kernel 1: ZE[v][r] = b[r] + sum_c Emb[v,c] * W[r,c]   (c in [0,256))
// =====================================================================
#define ZE_SWP 260
__global__ void __launch_bounds__(256) ze_kernel(const float* __restrict__ Emb,
                                                 const float* __restrict__ W,
                                                 const float* __restrict__ bias) {
    extern __shared__ float zsm[];
    float* sE = zsm;                    // 35*256 floats
    float* sW = zsm + NVOCAB * HID;     // 128*ZE_SWP floats
    const int tid = threadIdx.x, blk = blockIdx.x;

    for (int i = tid; i < (NVOCAB * HID) / 4; i += 256)
        *(float4*)&sE[i * 4] = *(const float4*)(Emb + i * 4);
    for (int i = tid; i < 128 * 64; i += 256) {
        int rl = i >> 6, c4 = i & 63;
        *(float4*)&sW[rl * ZE_SWP + c4 * 4] =
            *(const float4*)(W + (size_t)(blk * 128 + rl) * 512 + c4 * 4);
    }
    __syncthreads();

    for (int i = tid; i < 128 * NVOCAB; i += 256) {
        int rl = i % 128, v = i / 128;
        const float* we = sW + rl * ZE_SWP;
        const float* ee = sE + v * HID;
        float acc = 0.f;
        #pragma unroll 8
        for (int c = 0; c < HID; c++) acc = fmaf(we[c], ee[c], acc);
        g_ZE[v * ROWS7 + blk * 128 + rl] = acc + bias[blk * 128 + rl];
    }
}

// =====================================================================
// Kernel 2: persistent CT-LSTM reverse scan (R7 matvec core).
// 128 CTAs: cta = sg*16 + ug.  ug owns 16 hidden units (112 W rows in smem),
// sg owns 16 sequences.  Per-sg barriers on PRIVATE 512B lines.
// =====================================================================
#define SM_WS    (RPAD * HID)        // 32768 f : Ws[c*128 + rloc]
#define SM_HT    (HID * SPC)         //  4096 f : hT[c*16 + s]
#define SM_PART  (4 * SPC * PSTR)    //  8448 f : part[(kq*16+s)*132 + rloc]
#define SM_ZES   (NVOCAB * RPC)      //  3920 f
#define SM_EVS   (SPC * TLEN)        //  4096 (ints)
#define SM_DTS   (SPC * TLEN)        //  4096 f
#define SMEM_MAIN ((SM_WS + SM_HT + SM_PART + SM_ZES + SM_EVS + SM_DTS) * 4)

__global__ void __launch_bounds__(NTHR, 1)
ctlstm_kernel(const int* __restrict__ ev, const float* __restrict__ dtime,
              const float* __restrict__ W, float* __restrict__ out) {
    extern __shared__ float sm[];
    float* Ws   = sm;
    float* hT   = Ws + SM_WS;
    float* part = hT + SM_HT;
    float* ZEs  = part + SM_PART;
    int*   evs  = (int*)(ZEs + SM_ZES);
    float* dts  = (float*)(evs + SM_EVS);

    const int tid = threadIdx.x;
    const int cta = blockIdx.x;
    const int ug  = cta & 15;
    const int sg  = cta >> 4;

    unsigned* cntp = &g_cnt[sg * BPAD];
    unsigned* epp  = &g_ep[sg * BPAD];

    // pre-arrival epoch snapshot (all threads; replay-safe)
    const unsigned epoch0 = *(volatile unsigned*)epp;

    // ---- init: W slice (rows g*256 + ug*16+u, cols 256..511), c-major
    for (int i = tid; i < RPC * 64; i += NTHR) {
        int rl = i >> 6, c4 = i & 63;
        int g = rl >> 4, u = rl & 15;
        size_t rg = (size_t)(g * HID + ug * UPC + u);
        float4 w4 = *(const float4*)(W + rg * 512 + 256 + c4 * 4);
        Ws[(c4 * 4 + 0) * RPAD + rl] = w4.x;
        Ws[(c4 * 4 + 1) * RPAD + rl] = w4.y;
        Ws[(c4 * 4 + 2) * RPAD + rl] = w4.z;
        Ws[(c4 * 4 + 3) * RPAD + rl] = w4.w;
    }
    for (int i = tid; i < 16 * HID; i += NTHR) {            // zero pad rows
        int rl = RPC + (i & 15), c = i >> 4;
        Ws[c * RPAD + rl] = 0.f;
    }
    for (int i = tid; i < NVOCAB * RPC; i += NTHR) {        // ZE slice
        int v = i / RPC, rl = i % RPC;
        int g = rl >> 4, u = rl & 15;
        ZEs[v * RPC + rl] = g_ZE[v * ROWS7 + g * HID + ug * UPC + u];
    }
    for (int i = tid; i < SPC * TLEN / 4; i += NTHR) {      // event/dtime cache
        int s = i >> 6, c4 = i & 63;
        int seq = sg * SPC + s;
        *(int4*)&evs[s * TLEN + c4 * 4]   = *(const int4*)(ev + (size_t)seq * TLEN + c4 * 4);
        *(float4*)&dts[s * TLEN + c4 * 4] = *(const float4*)(dtime + (size_t)seq * TLEN + c4 * 4);
    }
    for (int i = tid; i < HID * SPC; i += NTHR) hT[i] = 0.f;   // h_plus starts 0
    __syncthreads();

    // matvec decomposition: warp = (kk, sb); lane rb = 4-row block
    const int kk = tid >> 6;           // K quarter: c in [kk*64, kk*64+64)
    const int sb = (tid >> 5) & 1;     // seq half: seqs [sb*8, sb*8+8)
    const int rb = tid & 31;           // rows [rb*4, rb*4+4)
    const int c0 = kk * 64;

    // reduce/gates decomposition: tid = s*16 + u
    const int s_id = tid >> 4;
    const int u_id = tid & 15;
    const int seqG  = sg * SPC + s_id;
    const int unitG = ug * UPC + u_id;
    const long long TS    = (long long)NSEQ * TOUT * HID;
    const long long obase = (long long)seqG * (TOUT * HID) + unitG;

    float cprev = 0.f, cbprev = 0.f;
    unsigned phase = 0;

    for (int t = TOUT - 1; t >= 0; --t) {
        // ---------- matvec: part = Ws-slice @ hT ----------
        unsigned long long acc[4][4];
        #pragma unroll
        for (int r = 0; r < 4; r++)
            #pragma unroll
            for (int p = 0; p < 4; p++) acc[r][p] = 0ull;

        const float* wp = Ws + c0 * RPAD + rb * 4;
        const ulonglong2* hp = (const ulonglong2*)(hT + c0 * 16 + sb * 8);
        #pragma unroll 4
        for (int c = 0; c < 64; ++c) {
            float4 w = *(const float4*)wp;  wp += RPAD;
            ulonglong2 hA = hp[0];
            ulonglong2 hB = hp[1];
            hp += 4;
            unsigned long long wd0 = pkdup(w.x), wd1 = pkdup(w.y);
            unsigned long long wd2 = pkdup(w.z), wd3 = pkdup(w.w);
            fma2(acc[0][0], wd0, hA.x); fma2(acc[1][0], wd1, hA.x);
            fma2(acc[2][0], wd2, hA.x); fma2(acc[3][0], wd3, hA.x);
            fma2(acc[0][1], wd0, hA.y); fma2(acc[1][1], wd1, hA.y);
            fma2(acc[2][1], wd2, hA.y); fma2(acc[3][1], wd3, hA.y);
            fma2(acc[0][2], wd0, hB.x); fma2(acc[1][2], wd1, hB.x);
            fma2(acc[2][2], wd2, hB.x); fma2(acc[3][2], wd3, hB.x);
            fma2(acc[0][3], wd0, hB.y); fma2(acc[1][3], wd1, hB.y);
            fma2(acc[2][3], wd2, hB.y); fma2(acc[3][3], wd3, hB.y);
        }
        #pragma unroll
        for (int p = 0; p < 4; p++) {
            float2 p0 = up2(acc[0][p]), p1 = up2(acc[1][p]);
            float2 p2 = up2(acc[2][p]), p3 = up2(acc[3][p]);
            float4 e4 = make_float4(p0.x, p1.x, p2.x, p3.x);
            float4 o4 = make_float4(p0.y, p1.y, p2.y, p3.y);
            *(float4*)&part[(kk * 16 + sb * 8 + 2 * p)     * PSTR + rb * 4] = e4;
            *(float4*)&part[(kk * 16 + sb * 8 + 2 * p + 1) * PSTR + rb * 4] = o4;
        }
        __syncthreads();

        // ---------- reduce + minimal chain to h ----------
        const int   e  = evs[s_id * TLEN + t + 1];
        const float dt = dts[s_id * TLEN + t + 1];
        float z[7];
        #pragma unroll
        for (int g = 0; g < 7; ++g) {
            int rl = g * 16 + u_id;
            float a = ZEs[e * RPC + rl];
            a += part[(0 * 16 + s_id) * PSTR + rl];
            a += part[(1 * 16 + s_id) * PSTR + rl];
            a += part[(2 * 16 + s_id) * PSTR + rl];
            a += part[(3 * 16 + s_id) * PSTR + rl];
            z[g] = a;
        }
        float gi  = sigm(z[0]);
        float gf  = sigm(z[1]);
        float go  = sigm(z[2]);
        float gz  = tanhf(z[3]);
        float gib = sigm(z[4]);
        float gfb = sigm(z[5]);
        float gd  = fmaxf(z[6], 0.f) + log1pf(__expf(-fabsf(z[6])));   // softplus

        float cell = gf * cprev + gi * gz;
        float cbar = gfb * cbprev + gib * gz;
        float dec  = __expf(-gd * dt);
        float cnx  = cbar + (cell - cbar) * dec;
        float h    = go * tanhf(cnx);
        float m    = (e != PADIDX) ? 1.f : 0.f;
        cnx *= m; cbar *= m; h *= m;

        long long ob = obase + (long long)t * HID;

        if (t > 0) {
            // publish h TRANSPOSED immediately: g_hT[unit][seqG]
            __stcg(&g_hT[(size_t)unitG * NSEQ + seqG], h);
            __threadfence();
            __syncthreads();
            // arrive FIRST (tid0), then everyone drains outputs, then all spin
            if (tid == 0) {
                unsigned old = atomicAdd(cntp, 1u);
                if (old == CPG - 1) {
                    *(volatile unsigned*)cntp = 0u;
                    __threadfence();
                    atomicAdd(epp, 1u);
                }
            }
            ++phase;

            // deferred math + outputs overlap the barrier window
            float hmin = go * tanhf(cell);
            out[ob]          = cell;
            out[TS + ob]     = cbar;
            out[2 * TS + ob] = gd;
            out[3 * TS + ob] = go;
            out[4 * TS + ob] = h;
            out[5 * TS + ob] = hmin;
            cprev = cnx; cbprev = cbar;

            // all-thread acquire spin on the group's private epoch line
            while (ld_acq(epp) - epoch0 < phase) { }

            // reload hT[c*16+s] — conflict-free contiguous STS.128
            for (int i = tid; i < (HID * SPC) / 4; i += NTHR) {
                int c = i >> 2, s4 = (i & 3) * 4;
                float4 hv = __ldcg((const float4*)(g_hT + (size_t)c * NSEQ + sg * SPC + s4));
                *(float4*)&hT[c * 16 + s4] = hv;
            }
            __syncthreads();
        } else {
            float hmin = go * tanhf(cell);
            out[ob]          = cell;
            out[TS + ob]     = cbar;
            out[2 * TS + ob] = gd;
            out[3 * TS + ob] = go;
            out[4 * TS + ob] = h;
            out[5 * TS + ob] = hmin;
        }
    }
}

// =====================================================================
extern "C" void kernel_launch(void* const* d_in, const int* in_sizes, int n_in,
                              void* d_out, int out_size) {
    const int*   ev    = (const int*)d_in[0];     // event_obs [16,8,256] int32
    const float* dt    = (const float*)d_in[1];   // dtime_obs [16,8,256]
    const float* Emb   = (const float*)d_in[2];   // [35,256]
    const float* W     = (const float*)d_in[3];   // [1792,512]
    const float* bias  = (const float*)d_in[4];   // [1792]
    float*       out   = (float*)d_out;           // 6 x [16,8,255,256]

    (void)in_sizes; (void)n_in; (void)out_size;

    const int ze_smem = (NVOCAB * HID + 128 * ZE_SWP) * 4;   // 168,960 B
    cudaFuncSetAttribute(ze_kernel, cudaFuncAttributeMaxDynamicSharedMemorySize, ze_smem);
    cudaFuncSetAttribute(ctlstm_kernel, cudaFuncAttributeMaxDynamicSharedMemorySize, SMEM_MAIN);

    ze_kernel<<<ROWS7 / 128, 256, ze_smem>>>(Emb, W, bias);
    ctlstm_kernel<<<NCTA, NTHR, SMEM_MAIN>>>(ev, dt, W, out);
}